// round 1
// baseline (speedup 1.0000x reference)
#include <cuda_runtime.h>
#include <math.h>

// Problem constants
#define NT 2048      // B*S tokens
#define ND 1024      // D
#define NH 4096      // H
#define NO 1024      // O
#define NE 8         // experts
#define CAP 2048     // max assignments per expert (each token picks an expert at most once)

// GEMM tiling
#define BM 64
#define BN 64
#define BK 16
#define ASTRIDE 68   // padded A row stride (68*4B = 272B = 17*16B, float4-aligned, conflict-free)

// Scratch (allocation-free rule: __device__ globals)
__device__ int   g_counts[NE];
__device__ int   g_rows[NE * CAP];         // assignment id a = token*2 + k
__device__ float g_wts [NE * CAP];         // renormalized top-k weight for that assignment
__device__ float g_h[(size_t)NT * 2 * NH]; // [4096][4096] fp32 hidden activations (64 MB)

// ---------------------------------------------------------------------------
// Zero output accumulator + expert counters
// ---------------------------------------------------------------------------
__global__ void zero_kernel(float* __restrict__ out, int n) {
    int i = blockIdx.x * blockDim.x + threadIdx.x;
    if (i < n) out[i] = 0.0f;
    if (i < NE) g_counts[i] = 0;
}

// ---------------------------------------------------------------------------
// Router: logits -> softmax -> top-2 -> renormalize -> scatter assignment lists
// One block per token; warp e computes logit for expert e.
// ---------------------------------------------------------------------------
__global__ void router_kernel(const float* __restrict__ x,
                              const float* __restrict__ Wr,
                              const float* __restrict__ br,
                              float* __restrict__ probs_out,
                              int write_probs) {
    __shared__ float sx[ND];
    __shared__ float slog[NE];
    int t = blockIdx.x;
    const float* xr = x + (size_t)t * ND;
    for (int i = threadIdx.x; i < ND; i += blockDim.x) sx[i] = xr[i];
    __syncthreads();

    int w = threadIdx.x >> 5;
    int lane = threadIdx.x & 31;
    float acc = 0.0f;
    for (int d = lane; d < ND; d += 32) acc += sx[d] * Wr[d * NE + w];
    #pragma unroll
    for (int o = 16; o; o >>= 1) acc += __shfl_xor_sync(0xffffffffu, acc, o);
    if (lane == 0) slog[w] = acc + br[w];
    __syncthreads();

    if (threadIdx.x == 0) {
        float p[NE];
        float mx = -1e30f;
        #pragma unroll
        for (int e = 0; e < NE; e++) mx = fmaxf(mx, slog[e]);
        float s = 0.0f;
        #pragma unroll
        for (int e = 0; e < NE; e++) { p[e] = expf(slog[e] - mx); s += p[e]; }
        float inv = 1.0f / s;
        #pragma unroll
        for (int e = 0; e < NE; e++) p[e] *= inv;

        // top-2 (strict > keeps lowest index on ties, matching lax.top_k)
        int i0 = 0;
        #pragma unroll
        for (int e = 1; e < NE; e++) if (p[e] > p[i0]) i0 = e;
        int i1 = (i0 == 0) ? 1 : 0;
        #pragma unroll
        for (int e = 0; e < NE; e++) if (e != i0 && p[e] > p[i1]) i1 = e;

        float wsum = p[i0] + p[i1];
        float w0 = p[i0] / wsum;
        float w1 = p[i1] / wsum;

        int pos0 = atomicAdd(&g_counts[i0], 1);
        g_rows[i0 * CAP + pos0] = t * 2;
        g_wts [i0 * CAP + pos0] = w0;
        int pos1 = atomicAdd(&g_counts[i1], 1);
        g_rows[i1 * CAP + pos1] = t * 2 + 1;
        g_wts [i1 * CAP + pos1] = w1;

        if (write_probs) {
            #pragma unroll
            for (int e = 0; e < NE; e++) probs_out[t * NE + e] = p[e];
        }
    }
}

// ---------------------------------------------------------------------------
// GEMM1: h[a,:] = gelu( x[token(a),:] @ W1[e] + b1[e] ), gathered rows per expert
// Tiled fp32 GEMM, 256 threads, 4x4 microtile, BM=BN=64, BK=16.
// ---------------------------------------------------------------------------
__global__ __launch_bounds__(256) void gemm1_kernel(const float* __restrict__ x,
                                                    const float* __restrict__ W1,
                                                    const float* __restrict__ b1) {
    int e = blockIdx.z;
    int cnt = g_counts[e];
    int m0 = blockIdx.y * BM;
    if (m0 >= cnt) return;
    int n0 = blockIdx.x * BN;

    __shared__ float As[BK][ASTRIDE];
    __shared__ float Bs[BK][BN];
    __shared__ int   sa[BM];

    int tid = threadIdx.x;
    if (tid < BM) {
        int m = m0 + tid;
        sa[tid] = (m < cnt) ? g_rows[e * CAP + m] : 0;
    }
    __syncthreads();

    const float* Wb = W1 + (size_t)e * ND * NH;

    float acc[4][4];
    #pragma unroll
    for (int i = 0; i < 4; i++)
        #pragma unroll
        for (int j = 0; j < 4; j++) acc[i][j] = 0.0f;

    int tx = tid & 15;
    int ty = tid >> 4;

    for (int k0 = 0; k0 < ND; k0 += BK) {
        #pragma unroll
        for (int l = 0; l < 4; l++) {
            int lin = tid + l * 256;
            int m = lin >> 4, k = lin & 15;
            As[k][m] = x[(size_t)(sa[m] >> 1) * ND + k0 + k];
        }
        {
            int lin = tid * 4;
            int k = lin >> 6, nn = lin & 63;
            *reinterpret_cast<float4*>(&Bs[k][nn]) =
                *reinterpret_cast<const float4*>(&Wb[(size_t)(k0 + k) * NH + n0 + nn]);
        }
        __syncthreads();
        #pragma unroll
        for (int k = 0; k < BK; k++) {
            float4 a4 = *reinterpret_cast<const float4*>(&As[k][ty * 4]);
            float4 b4 = *reinterpret_cast<const float4*>(&Bs[k][tx * 4]);
            float ra[4] = {a4.x, a4.y, a4.z, a4.w};
            float rb[4] = {b4.x, b4.y, b4.z, b4.w};
            #pragma unroll
            for (int i = 0; i < 4; i++)
                #pragma unroll
                for (int j = 0; j < 4; j++)
                    acc[i][j] += ra[i] * rb[j];
        }
        __syncthreads();
    }

    #pragma unroll
    for (int i = 0; i < 4; i++) {
        int m = ty * 4 + i;
        if (m0 + m >= cnt) continue;
        int a = sa[m];
        #pragma unroll
        for (int j = 0; j < 4; j++) {
            int col = n0 + tx * 4 + j;
            float v = acc[i][j] + b1[e * NH + col];
            v = 0.5f * v * (1.0f + erff(v * 0.70710678118654752f));  // exact-erf GELU
            g_h[(size_t)a * NH + col] = v;
        }
    }
}

// ---------------------------------------------------------------------------
// GEMM2: out[token,:] += wt * ( h[a,:] @ W2[e] + b2[e] )
// ---------------------------------------------------------------------------
__global__ __launch_bounds__(256) void gemm2_kernel(const float* __restrict__ W2,
                                                    const float* __restrict__ b2,
                                                    float* __restrict__ out) {
    int e = blockIdx.z;
    int cnt = g_counts[e];
    int m0 = blockIdx.y * BM;
    if (m0 >= cnt) return;
    int n0 = blockIdx.x * BN;

    __shared__ float As[BK][ASTRIDE];
    __shared__ float Bs[BK][BN];
    __shared__ int   sa[BM];
    __shared__ float sw[BM];

    int tid = threadIdx.x;
    if (tid < BM) {
        int m = m0 + tid;
        sa[tid] = (m < cnt) ? g_rows[e * CAP + m] : 0;
        sw[tid] = (m < cnt) ? g_wts [e * CAP + m] : 0.0f;
    }
    __syncthreads();

    const float* Wb = W2 + (size_t)e * NH * NO;

    float acc[4][4];
    #pragma unroll
    for (int i = 0; i < 4; i++)
        #pragma unroll
        for (int j = 0; j < 4; j++) acc[i][j] = 0.0f;

    int tx = tid & 15;
    int ty = tid >> 4;

    for (int k0 = 0; k0 < NH; k0 += BK) {
        #pragma unroll
        for (int l = 0; l < 4; l++) {
            int lin = tid + l * 256;
            int m = lin >> 4, k = lin & 15;
            As[k][m] = g_h[(size_t)sa[m] * NH + k0 + k];
        }
        {
            int lin = tid * 4;
            int k = lin >> 6, nn = lin & 63;
            *reinterpret_cast<float4*>(&Bs[k][nn]) =
                *reinterpret_cast<const float4*>(&Wb[(size_t)(k0 + k) * NO + n0 + nn]);
        }
        __syncthreads();
        #pragma unroll
        for (int k = 0; k < BK; k++) {
            float4 a4 = *reinterpret_cast<const float4*>(&As[k][ty * 4]);
            float4 b4 = *reinterpret_cast<const float4*>(&Bs[k][tx * 4]);
            float ra[4] = {a4.x, a4.y, a4.z, a4.w};
            float rb[4] = {b4.x, b4.y, b4.z, b4.w};
            #pragma unroll
            for (int i = 0; i < 4; i++)
                #pragma unroll
                for (int j = 0; j < 4; j++)
                    acc[i][j] += ra[i] * rb[j];
        }
        __syncthreads();
    }

    #pragma unroll
    for (int i = 0; i < 4; i++) {
        int m = ty * 4 + i;
        if (m0 + m >= cnt) continue;
        int a = sa[m];
        int token = a >> 1;
        float wt = sw[m];
        #pragma unroll
        for (int j = 0; j < 4; j++) {
            int col = n0 + tx * 4 + j;
            float v = (acc[i][j] + b2[e * NO + col]) * wt;
            atomicAdd(&out[(size_t)token * NO + col], v);
        }
    }
}

// ---------------------------------------------------------------------------
// Launch
// ---------------------------------------------------------------------------
extern "C" void kernel_launch(void* const* d_in, const int* in_sizes, int n_in,
                              void* d_out, int out_size) {
    const float* x  = (const float*)d_in[0];
    const float* Wr = (const float*)d_in[1];
    const float* br = (const float*)d_in[2];
    const float* W1 = (const float*)d_in[3];
    const float* b1 = (const float*)d_in[4];
    const float* W2 = (const float*)d_in[5];
    const float* b2 = (const float*)d_in[6];
    float* out = (float*)d_out;

    const int main_n = NT * NO;                       // 2,097,152
    int write_probs = (out_size >= main_n + NT * NE) ? 1 : 0;

    zero_kernel<<<(main_n + 255) / 256, 256>>>(out, main_n);
    router_kernel<<<NT, 256>>>(x, Wr, br, out + main_n, write_probs);
    gemm1_kernel<<<dim3(NH / BN, CAP / BM, NE), 256>>>(x, W1, b1);
    gemm2_kernel<<<dim3(NO / BN, CAP / BM, NE), 256>>>(W2, b2, out);
}

// round 2
// speedup vs baseline: 3.5913x; 3.5913x over previous
#include <cuda_runtime.h>
#include <math.h>
#include <stdint.h>

// Problem constants
#define NT 2048      // B*S tokens
#define ND 1024      // D
#define NH 4096      // H
#define NO 1024      // O
#define NE 8         // experts
#define CAP 2048     // max assignments per expert
#define NROWS (NT*2) // total assignments = 4096

// GEMM tiling
#define BM 128
#define BN 128
#define BK 16
#define ASTR 20      // A smem row stride (floats) -> conflict-free frag loads
#define BSTR 136     // B smem row stride (floats) -> conflict-free frag loads

// Scratch (allocation-free rule: __device__ globals)
__device__ int   g_counts[NE];
__device__ int   g_off[NE];
__device__ int   g_rows[NE * CAP];            // assignment id a = token*2 + k
__device__ float g_wts [NE * CAP];            // renormalized top-k weight
__device__ float g_h[(size_t)NROWS * NH];     // compacted hidden activations (64 MB)

// ---------------------------------------------------------------------------
// helpers
// ---------------------------------------------------------------------------
__device__ __forceinline__ uint32_t f2tf32(float f) {
    uint32_t u;
    asm("cvt.rna.tf32.f32 %0, %1;" : "=r"(u) : "f"(f));
    return u;
}

__device__ __forceinline__ void mma_tf32(float* c, const uint32_t* a, const uint32_t* b) {
    asm volatile(
        "mma.sync.aligned.m16n8k8.row.col.f32.tf32.tf32.f32 "
        "{%0,%1,%2,%3}, {%4,%5,%6,%7}, {%8,%9}, {%0,%1,%2,%3};"
        : "+f"(c[0]), "+f"(c[1]), "+f"(c[2]), "+f"(c[3])
        : "r"(a[0]), "r"(a[1]), "r"(a[2]), "r"(a[3]), "r"(b[0]), "r"(b[1]));
}

__device__ __forceinline__ void cp16(void* smem, const void* g) {
    uint32_t s = (uint32_t)__cvta_generic_to_shared(smem);
    asm volatile("cp.async.cg.shared.global [%0], [%1], 16;" :: "r"(s), "l"(g));
}
__device__ __forceinline__ void cp_commit() { asm volatile("cp.async.commit_group;"); }
__device__ __forceinline__ void cp_wait0()  { asm volatile("cp.async.wait_group 0;"); }

// ---------------------------------------------------------------------------
// Zero output accumulator + expert counters
// ---------------------------------------------------------------------------
__global__ void zero_kernel(float* __restrict__ out, int n) {
    int i = blockIdx.x * blockDim.x + threadIdx.x;
    if (i < n) out[i] = 0.0f;
    if (i < NE) g_counts[i] = 0;
}

// ---------------------------------------------------------------------------
// Router: logits -> softmax -> top-2 -> renormalize -> scatter assignment lists
// ---------------------------------------------------------------------------
__global__ void router_kernel(const float* __restrict__ x,
                              const float* __restrict__ Wr,
                              const float* __restrict__ br,
                              float* __restrict__ probs_out,
                              int write_probs) {
    __shared__ float sx[ND];
    __shared__ float slog[NE];
    int t = blockIdx.x;
    const float* xr = x + (size_t)t * ND;
    for (int i = threadIdx.x; i < ND; i += blockDim.x) sx[i] = xr[i];
    __syncthreads();

    int w = threadIdx.x >> 5;
    int lane = threadIdx.x & 31;
    float acc = 0.0f;
    for (int d = lane; d < ND; d += 32) acc += sx[d] * Wr[d * NE + w];
    #pragma unroll
    for (int o = 16; o; o >>= 1) acc += __shfl_xor_sync(0xffffffffu, acc, o);
    if (lane == 0) slog[w] = acc + br[w];
    __syncthreads();

    if (threadIdx.x == 0) {
        float p[NE];
        float mx = -1e30f;
        #pragma unroll
        for (int e = 0; e < NE; e++) mx = fmaxf(mx, slog[e]);
        float s = 0.0f;
        #pragma unroll
        for (int e = 0; e < NE; e++) { p[e] = expf(slog[e] - mx); s += p[e]; }
        float inv = 1.0f / s;
        #pragma unroll
        for (int e = 0; e < NE; e++) p[e] *= inv;

        int i0 = 0;
        #pragma unroll
        for (int e = 1; e < NE; e++) if (p[e] > p[i0]) i0 = e;
        int i1 = (i0 == 0) ? 1 : 0;
        #pragma unroll
        for (int e = 0; e < NE; e++) if (e != i0 && p[e] > p[i1]) i1 = e;

        float wsum = p[i0] + p[i1];
        float w0 = p[i0] / wsum;
        float w1 = p[i1] / wsum;

        int pos0 = atomicAdd(&g_counts[i0], 1);
        g_rows[i0 * CAP + pos0] = t * 2;
        g_wts [i0 * CAP + pos0] = w0;
        int pos1 = atomicAdd(&g_counts[i1], 1);
        g_rows[i1 * CAP + pos1] = t * 2 + 1;
        g_wts [i1 * CAP + pos1] = w1;

        if (write_probs) {
            #pragma unroll
            for (int e = 0; e < NE; e++) probs_out[t * NE + e] = p[e];
        }
    }
}

// ---------------------------------------------------------------------------
// Prefix: exclusive scan of expert counts (8 values)
// ---------------------------------------------------------------------------
__global__ void prefix_kernel() {
    if (threadIdx.x == 0) {
        int s = 0;
        #pragma unroll
        for (int e = 0; e < NE; e++) { g_off[e] = s; s += g_counts[e]; }
    }
}

// ---------------------------------------------------------------------------
// Grouped GEMM on tf32 tensor cores (mma.sync m16n8k8).
// IS_G1: C = gelu( gather(x) @ W1[e] + b1[e] ) -> g_h (compacted rows)
// else : out[token] += wt * ( g_h @ W2[e] + b2[e] )   (atomic combine)
// Block 128x128, BK=16, 8 warps (2x4), warp tile 64x32, cp.async double buffer.
// ---------------------------------------------------------------------------
template<int KTOT, int NCOLS, bool IS_G1>
__global__ __launch_bounds__(256) void moe_gemm(const float* __restrict__ Asrc,
                                                const float* __restrict__ Wall,
                                                const float* __restrict__ ball,
                                                float* __restrict__ outp) {
    __shared__ float As[2][BM][ASTR];
    __shared__ float Bs[2][BK][BSTR];
    __shared__ int   sa[BM];
    __shared__ float sw[BM];

    int e = blockIdx.z;
    int cnt = g_counts[e];
    int m0 = blockIdx.y * BM;
    if (m0 >= cnt) return;
    int n0 = blockIdx.x * BN;
    int base = g_off[e];

    int tid = threadIdx.x;
    int lane = tid & 31;
    int wid = tid >> 5;
    int warpM = wid >> 2;   // 0..1
    int warpN = wid & 3;    // 0..3

    if (tid < BM) {
        int m = m0 + tid;
        sa[tid] = (m < cnt) ? g_rows[e * CAP + m] : 0;
        sw[tid] = (m < cnt) ? g_wts [e * CAP + m] : 0.0f;
    }
    __syncthreads();

    const float* W = Wall + (size_t)e * KTOT * NCOLS;

    // Per-thread async-copy task coordinates (2 A chunks + 2 B chunks / iter)
    int am0 = tid >> 2;             int ac = (tid & 3) * 4;
    int am1 = am0 + 64;
    int bk0 = tid >> 5;             int bc = (tid & 31) * 4;
    int bk1 = bk0 + 8;

    const float* arow0;
    const float* arow1;
    if (IS_G1) {
        arow0 = Asrc + (size_t)(sa[am0] >> 1) * KTOT;
        arow1 = Asrc + (size_t)(sa[am1] >> 1) * KTOT;
    } else {
        int r0 = m0 + am0; if (r0 > cnt - 1) r0 = cnt - 1;
        int r1 = m0 + am1; if (r1 > cnt - 1) r1 = cnt - 1;
        arow0 = Asrc + (size_t)(base + r0) * KTOT;
        arow1 = Asrc + (size_t)(base + r1) * KTOT;
    }
    const float* brow0 = W + (size_t)bk0 * NCOLS + n0 + bc;
    const float* brow1 = W + (size_t)bk1 * NCOLS + n0 + bc;

    float cacc[4][4][4];
    #pragma unroll
    for (int mi = 0; mi < 4; mi++)
        #pragma unroll
        for (int ni = 0; ni < 4; ni++)
            #pragma unroll
            for (int q = 0; q < 4; q++) cacc[mi][ni][q] = 0.0f;

    const int KIT = KTOT / BK;

    // Prologue: load tile 0
    cp16(&As[0][am0][ac], arow0 + ac);
    cp16(&As[0][am1][ac], arow1 + ac);
    cp16(&Bs[0][bk0][bc], brow0);
    cp16(&Bs[0][bk1][bc], brow1);
    cp_commit();

    int buf = 0;
    int g = lane >> 2, t4 = lane & 3;

    for (int it = 0; it < KIT; it++) {
        cp_wait0();
        __syncthreads();

        if (it + 1 < KIT) {
            int k0 = (it + 1) * BK;
            int nb = buf ^ 1;
            cp16(&As[nb][am0][ac], arow0 + k0 + ac);
            cp16(&As[nb][am1][ac], arow1 + k0 + ac);
            cp16(&Bs[nb][bk0][bc], brow0 + (size_t)k0 * NCOLS);
            cp16(&Bs[nb][bk1][bc], brow1 + (size_t)k0 * NCOLS);
            cp_commit();
        }

        #pragma unroll
        for (int kk = 0; kk < 2; kk++) {
            uint32_t a[4][4], b[4][2];
            int k = kk * 8 + t4;
            #pragma unroll
            for (int mi = 0; mi < 4; mi++) {
                int r = warpM * 64 + mi * 16 + g;
                a[mi][0] = f2tf32(As[buf][r    ][k    ]);
                a[mi][1] = f2tf32(As[buf][r + 8][k    ]);
                a[mi][2] = f2tf32(As[buf][r    ][k + 4]);
                a[mi][3] = f2tf32(As[buf][r + 8][k + 4]);
            }
            #pragma unroll
            for (int ni = 0; ni < 4; ni++) {
                int cN = warpN * 32 + ni * 8 + g;
                b[ni][0] = f2tf32(Bs[buf][k    ][cN]);
                b[ni][1] = f2tf32(Bs[buf][k + 4][cN]);
            }
            #pragma unroll
            for (int mi = 0; mi < 4; mi++)
                #pragma unroll
                for (int ni = 0; ni < 4; ni++)
                    mma_tf32(cacc[mi][ni], a[mi], b[ni]);
        }
        buf ^= 1;
    }

    // Epilogue
    #pragma unroll
    for (int mi = 0; mi < 4; mi++) {
        #pragma unroll
        for (int hi = 0; hi < 2; hi++) {
            int rloc = warpM * 64 + mi * 16 + g + hi * 8;
            if (m0 + rloc >= cnt) continue;
            #pragma unroll
            for (int ni = 0; ni < 4; ni++) {
                int col = n0 + warpN * 32 + ni * 8 + 2 * t4;
                float v0 = cacc[mi][ni][hi * 2 + 0];
                float v1 = cacc[mi][ni][hi * 2 + 1];
                float bv0 = ball[e * NCOLS + col];
                float bv1 = ball[e * NCOLS + col + 1];
                if (IS_G1) {
                    v0 += bv0; v1 += bv1;
                    v0 = 0.5f * v0 * (1.0f + erff(v0 * 0.70710678118654752f));
                    v1 = 0.5f * v1 * (1.0f + erff(v1 * 0.70710678118654752f));
                    size_t gid = (size_t)(base + m0 + rloc);
                    float2 st = make_float2(v0, v1);
                    *reinterpret_cast<float2*>(&outp[gid * NCOLS + col]) = st;
                } else {
                    int token = sa[rloc] >> 1;
                    float wt = sw[rloc];
                    atomicAdd(&outp[(size_t)token * NCOLS + col    ], (v0 + bv0) * wt);
                    atomicAdd(&outp[(size_t)token * NCOLS + col + 1], (v1 + bv1) * wt);
                }
            }
        }
    }
}

// ---------------------------------------------------------------------------
// Launch
// ---------------------------------------------------------------------------
extern "C" void kernel_launch(void* const* d_in, const int* in_sizes, int n_in,
                              void* d_out, int out_size) {
    const float* x  = (const float*)d_in[0];
    const float* Wr = (const float*)d_in[1];
    const float* br = (const float*)d_in[2];
    const float* W1 = (const float*)d_in[3];
    const float* b1 = (const float*)d_in[4];
    const float* W2 = (const float*)d_in[5];
    const float* b2 = (const float*)d_in[6];
    float* out = (float*)d_out;

    const int main_n = NT * NO;
    int write_probs = (out_size >= main_n + NT * NE) ? 1 : 0;

    float* g_h_ptr = nullptr;
    cudaGetSymbolAddress((void**)&g_h_ptr, g_h);

    zero_kernel<<<(main_n + 255) / 256, 256>>>(out, main_n);
    router_kernel<<<NT, 256>>>(x, Wr, br, out + main_n, write_probs);
    prefix_kernel<<<1, 32>>>();
    moe_gemm<ND, NH, true ><<<dim3(NH / BN, CAP / BM, NE), 256>>>(x, W1, b1, g_h_ptr);
    moe_gemm<NH, NO, false><<<dim3(NO / BN, CAP / BM, NE), 256>>>(g_h_ptr, W2, b2, out);
}